// round 8
// baseline (speedup 1.0000x reference)
#include <cuda_runtime.h>
#include <math.h>

#define BB   4
#define HWSZ 16384        // 128*128

// ---------------- scratch (device globals: no allocation allowed) ----------------
__device__ float g_highup[16777216];  // (4,256,128,128)
__device__ float g_query [ 8388608];  // (4,128,128,128)
__device__ float g_value [ 8388608];
__device__ float g_pv    [ 8388608];
__device__ float g_tmp   [ 8388608];  // unnormalized outH
__device__ float g_pq    [ 1048576];  // (4,16,128,128)
__device__ float g_pk    [ 1048576];
__device__ float g_tot   [   65536];  // (4,128,128) sumH (then consumed by fusedW)

// ---------------- tf32 helpers ----------------
__device__ __forceinline__ unsigned f2tf(float f) {
    unsigned r;
    asm("cvt.rna.tf32.f32 %0, %1;" : "=r"(r) : "f"(f));
    return r;
}

__device__ __forceinline__ void mma8(float* d, const unsigned* a, const unsigned* b) {
    asm("mma.sync.aligned.m16n8k8.row.col.f32.tf32.tf32.f32 "
        "{%0,%1,%2,%3},{%4,%5,%6,%7},{%8,%9},{%0,%1,%2,%3};"
        : "+f"(d[0]), "+f"(d[1]), "+f"(d[2]), "+f"(d[3])
        : "r"(a[0]), "r"(a[1]), "r"(a[2]), "r"(a[3]), "r"(b[0]), "r"(b[1]));
}

// One K=16 chunk from staged smem tiles. Warp tile 64x32 (4 m x 4 n of 16x8 mmas).
__device__ __forceinline__ void tile_mma(const unsigned (*As)[136],
                                         const unsigned (*Bs)[136],
                                         float acc[4][4][4],
                                         int lane, int mbase, int nbase)
{
#pragma unroll
    for (int kt = 0; kt < 2; kt++) {
        unsigned a[4][4], b[4][2];
        const int kb = kt * 8 + (lane & 3);
        const int rq = lane >> 2;
#pragma unroll
        for (int mt = 0; mt < 4; mt++) {
            int m = mbase + mt * 16 + rq;
            a[mt][0] = As[kb][m];
            a[mt][1] = As[kb][m + 8];
            a[mt][2] = As[kb + 4][m];
            a[mt][3] = As[kb + 4][m + 8];
        }
#pragma unroll
        for (int nt = 0; nt < 4; nt++) {
            int n = nbase + nt * 8 + rq;
            b[nt][0] = Bs[kb][n];
            b[nt][1] = Bs[kb + 4][n];
        }
#pragma unroll
        for (int mt = 0; mt < 4; mt++)
#pragma unroll
            for (int nt = 0; nt < 4; nt++)
                mma8(acc[mt][nt], a[mt], b[nt]);
    }
}

// ---------------- bilinear 2x upsample ----------------
__global__ __launch_bounds__(256) void upsample_kernel(const float* __restrict__ in,
                                                       float* __restrict__ out) {
    int idx = blockIdx.x * 256 + threadIdx.x;
    int ox = idx & 127;
    int oy = (idx >> 7) & 127;
    int bc = idx >> 14;
    float fy = 0.5f * oy - 0.25f;
    float fx = 0.5f * ox - 0.25f;
    int y0 = (int)floorf(fy); float wy = fy - (float)y0;
    int x0 = (int)floorf(fx); float wx = fx - (float)x0;
    int y1 = min(y0 + 1, 63); y0 = max(y0, 0);
    int x1 = min(x0 + 1, 63); x0 = max(x0, 0);
    const float* p = in + (size_t)bc * 4096;
    float v00 = p[y0 * 64 + x0], v01 = p[y0 * 64 + x1];
    float v10 = p[y1 * 64 + x0], v11 = p[y1 * 64 + x1];
    float top = v00 + wx * (v01 - v00);
    float bot = v10 + wx * (v11 - v10);
    out[idx] = top + wy * (bot - top);
}

// ---------------- dual-input tf32 GEMM (single-buffered, R4-proven) ----------------
__global__ __launch_bounds__(256) void gemm_dual(
    const float* __restrict__ Wm, int ldw,
    const float* __restrict__ bias,
    const float* __restrict__ X1, int I1,
    const float* __restrict__ X2, int I2,
    float* __restrict__ Y, int O,
    const float* __restrict__ bng, const float* __restrict__ bnb,
    const float* __restrict__ bnm, const float* __restrict__ bnv)
{
    __shared__ unsigned As[16][136];
    __shared__ unsigned Bs[16][136];
    const int b  = blockIdx.z;
    const int to = blockIdx.y * 128;
    const int tp = blockIdx.x * 128;
    const int tid  = threadIdx.x;
    const int warp = tid >> 5;
    const int lane = tid & 31;
    const int mbase = (warp >> 2) * 64;
    const int nbase = (warp & 3) * 32;

    const int am  = tid >> 1;
    const int akq = (tid & 1) * 8;
    const int bk  = tid >> 4;
    const int bn  = (tid & 15) * 8;

    const float* X1p = X1 + (size_t)b * I1 * HWSZ;
    const float* X2p = X2 ? X2 + (size_t)b * I2 * HWSZ : nullptr;
    const int K = I1 + I2;

    float acc[4][4][4] = {};

    for (int k0 = 0; k0 < K; k0 += 16) {
        const float* Wp = Wm + (size_t)(to + am) * ldw + k0 + akq;
        float4 w0 = *(const float4*)Wp;
        float4 w1 = *(const float4*)(Wp + 4);
        int kr = k0 + bk;
        const float* Xp = (kr < I1) ? (X1p + (size_t)kr * HWSZ)
                                    : (X2p + (size_t)(kr - I1) * HWSZ);
        Xp += tp + bn;
        float4 x0 = *(const float4*)Xp;
        float4 x1 = *(const float4*)(Xp + 4);

        __syncthreads();
        As[akq + 0][am] = f2tf(w0.x);
        As[akq + 1][am] = f2tf(w0.y);
        As[akq + 2][am] = f2tf(w0.z);
        As[akq + 3][am] = f2tf(w0.w);
        As[akq + 4][am] = f2tf(w1.x);
        As[akq + 5][am] = f2tf(w1.y);
        As[akq + 6][am] = f2tf(w1.z);
        As[akq + 7][am] = f2tf(w1.w);
        *(uint4*)&Bs[bk][bn]     = make_uint4(f2tf(x0.x), f2tf(x0.y), f2tf(x0.z), f2tf(x0.w));
        *(uint4*)&Bs[bk][bn + 4] = make_uint4(f2tf(x1.x), f2tf(x1.y), f2tf(x1.z), f2tf(x1.w));
        __syncthreads();

        tile_mma(As, Bs, acc, lane, mbase, nbase);
    }

    const bool dobn = (bng != nullptr);
#pragma unroll
    for (int mt = 0; mt < 4; mt++) {
#pragma unroll
        for (int half = 0; half < 2; half++) {
            int o = to + mbase + mt * 16 + (lane >> 2) + half * 8;
            float bia = bias ? bias[o] : 0.0f;
            float sc = 1.0f, mn = 0.0f, bt = 0.0f;
            if (dobn) {
                sc = bng[o] * rsqrtf(bnv[o] + 1e-5f);
                mn = bnm[o];
                bt = bnb[o];
            }
            size_t rowb = ((size_t)b * O + o) * HWSZ + tp;
#pragma unroll
            for (int nt = 0; nt < 4; nt++) {
                int n = nbase + nt * 8 + 2 * (lane & 3);
                float v0 = acc[mt][nt][half * 2 + 0] + bia;
                float v1 = acc[mt][nt][half * 2 + 1] + bia;
                if (dobn) {
                    v0 = fmaxf((v0 - mn) * sc + bt, 0.0f);
                    v1 = fmaxf((v1 - mn) * sc + bt, 0.0f);
                }
                *(float2*)(Y + rowb + n) = make_float2(v0, v1);
            }
        }
    }
}

// ---------------- small projection O=16, I=128 (R4-proven scalar version) ----------------
__global__ __launch_bounds__(256) void proj16_kernel(
    const float* __restrict__ Wm, const float* __restrict__ bias,
    const float* __restrict__ X, float* __restrict__ Y)
{
    __shared__ float Ws[16 * 128];
    const int b = blockIdx.y;
    const int p = blockIdx.x * 256 + threadIdx.x;
    for (int i = threadIdx.x; i < 2048; i += 256) Ws[i] = Wm[i];
    __syncthreads();
    float acc[16];
#pragma unroll
    for (int o = 0; o < 16; o++) acc[o] = bias[o];
    const float* Xp = X + (size_t)b * 128 * HWSZ + p;
#pragma unroll 4
    for (int i = 0; i < 128; i++) {
        float xv = Xp[(size_t)i * HWSZ];
#pragma unroll
        for (int o = 0; o < 16; o++) acc[o] += Ws[o * 128 + i] * xv;
    }
    float* Yp = Y + (size_t)b * 16 * HWSZ + p;
#pragma unroll
    for (int o = 0; o < 16; o++) Yp[(size_t)o * HWSZ] = acc[o];
}

// ---------------- fused attention kernels: E never touches HBM ----------------
// dynamic smem layout (bytes):
#define OFF_PQ   0            // float[16][128]   8192
#define OFF_PK   8192         // float[16][128]   8192
#define OFF_ES   16384        // unsigned[128][136]  69632
#define OFF_AS   86016        // unsigned[2][16][136] 17408
#define OFF_SSUM 103424       // float[2][128]    1024
#define OFF_INV  104448       // float[128]       512
#define FUSED_SMEM 104960

// fusedH (block b,w): E[h,x]=exp(pq(h)·pk(x)) (0 on diag), tot=sumH,
//                     U[c,h]=sum_x pv[b,c,x,w]*E[h,x] -> tmp (unnormalized)
__global__ __launch_bounds__(256) void fusedH_kernel(
    const float* __restrict__ pq, const float* __restrict__ pk,
    const float* __restrict__ pv, float* __restrict__ tot,
    float* __restrict__ tmp)
{
    extern __shared__ char sm[];
    float    (*PQ)[128]      = (float(*)[128])(sm + OFF_PQ);
    float    (*PK)[128]      = (float(*)[128])(sm + OFF_PK);
    unsigned (*Es)[136]      = (unsigned(*)[136])(sm + OFF_ES);
    unsigned (*As_)[16][136] = (unsigned(*)[16][136])(sm + OFF_AS);
    float    (*ssum)[128]    = (float(*)[128])(sm + OFF_SSUM);

    const int w = blockIdx.x, b = blockIdx.y;
    const int tid  = threadIdx.x;
    const int warp = tid >> 5, lane = tid & 31;
    const int mbase = (warp >> 2) * 64, nbase = (warp & 3) * 32;

    // phase 1: columns of pq/pk at width w
    for (int i = tid; i < 2048; i += 256) {
        int c = i >> 7, h = i & 127;
        size_t idx = (((size_t)b * 16 + c) * 128 + h) * 128 + w;
        PQ[c][h] = pq[idx];
        PK[c][h] = pk[idx];
    }
    __syncthreads();

    // phase 2: per-thread row h, loop x; register row-sum (no shuffles)
    {
        const int h = tid & 127;
        const int half = tid >> 7;
        const int x0 = half * 64;
        float sum = 0.0f;
        for (int x = x0; x < x0 + 64; x++) {
            float s0 = 0.f, s1 = 0.f, s2 = 0.f, s3 = 0.f;
#pragma unroll
            for (int c = 0; c < 16; c += 4) {
                s0 += PQ[c + 0][h] * PK[c + 0][x];
                s1 += PQ[c + 1][h] * PK[c + 1][x];
                s2 += PQ[c + 2][h] * PK[c + 2][x];
                s3 += PQ[c + 3][h] * PK[c + 3][x];
            }
            float e = (h == x) ? 0.0f : __expf((s0 + s1) + (s2 + s3));
            Es[x][h] = f2tf(e);
            sum += e;
        }
        ssum[half][h] = sum;
    }
    __syncthreads();
    if (tid < 128)
        tot[((size_t)b * 128 + tid) * 128 + w] = ssum[0][tid] + ssum[1][tid];

    // phase 3: U = pv @ E^T via tf32 mma; B operand = Es resident in smem
    const int cm = tid >> 1;
    const int xq = (tid & 1) * 8;
    const float* pvp = pv + ((size_t)b * 128 + cm) * HWSZ + w;

    float acc[4][4][4] = {};
    float av[8];
    auto loadA = [&](int x0) {
#pragma unroll
        for (int j = 0; j < 8; j++) av[j] = pvp[(size_t)(x0 + xq + j) * 128];
    };
    auto stA = [&](int buf) {
#pragma unroll
        for (int j = 0; j < 8; j++) As_[buf][xq + j][cm] = f2tf(av[j]);
    };
    loadA(0); stA(0);
    __syncthreads();
    for (int kt = 0; kt < 8; kt++) {
        if (kt < 7) loadA((kt + 1) * 16);
        tile_mma(As_[kt & 1], (const unsigned(*)[136])&Es[kt * 16], acc, lane, mbase, nbase);
        if (kt < 7) stA((kt + 1) & 1);
        __syncthreads();
    }

#pragma unroll
    for (int mt = 0; mt < 4; mt++)
#pragma unroll
        for (int half = 0; half < 2; half++) {
            int c = mbase + mt * 16 + (lane >> 2) + half * 8;
            size_t cb = ((size_t)b * 128 + c) * HWSZ + w;
#pragma unroll
            for (int nt = 0; nt < 4; nt++) {
                int h = nbase + nt * 8 + 2 * (lane & 3);
                tmp[cb + (size_t)h * 128]       = acc[mt][nt][half * 2 + 0];
                tmp[cb + (size_t)(h + 1) * 128] = acc[mt][nt][half * 2 + 1];
            }
        }
}

// fusedW (block b,h): E[w,x]=exp(pq(w)·pk(x)); inv=1/(sumH+sumW);
//                     value[c,h,w] += gamma*(U[c,h,w] + V[c,w])*inv[w]
__global__ __launch_bounds__(256) void fusedW_kernel(
    const float* __restrict__ pq, const float* __restrict__ pk,
    const float* __restrict__ pv, const float* __restrict__ tot,
    const float* __restrict__ tmp, float* __restrict__ value,
    const float* __restrict__ gamma_p)
{
    extern __shared__ char sm[];
    float    (*PQ)[128]      = (float(*)[128])(sm + OFF_PQ);
    float    (*PK)[128]      = (float(*)[128])(sm + OFF_PK);
    unsigned (*Es)[136]      = (unsigned(*)[136])(sm + OFF_ES);
    unsigned (*As_)[16][136] = (unsigned(*)[16][136])(sm + OFF_AS);
    float    (*ssum)[128]    = (float(*)[128])(sm + OFF_SSUM);
    float    *invs           = (float*)(sm + OFF_INV);

    const int h = blockIdx.x, b = blockIdx.y;
    const int tid  = threadIdx.x;
    const int warp = tid >> 5, lane = tid & 31;
    const int mbase = (warp >> 2) * 64, nbase = (warp & 3) * 32;

    // phase 1: rows of pq/pk at height h (contiguous)
    for (int i = tid; i < 2048; i += 256) {
        int c = i >> 7, x = i & 127;
        size_t idx = (((size_t)b * 16 + c) * 128 + h) * 128 + x;
        PQ[c][x] = pq[idx];
        PK[c][x] = pk[idx];
    }
    __syncthreads();

    // phase 2
    {
        const int wv = tid & 127;
        const int half = tid >> 7;
        const int x0 = half * 64;
        float sum = 0.0f;
        for (int x = x0; x < x0 + 64; x++) {
            float s0 = 0.f, s1 = 0.f, s2 = 0.f, s3 = 0.f;
#pragma unroll
            for (int c = 0; c < 16; c += 4) {
                s0 += PQ[c + 0][wv] * PK[c + 0][x];
                s1 += PQ[c + 1][wv] * PK[c + 1][x];
                s2 += PQ[c + 2][wv] * PK[c + 2][x];
                s3 += PQ[c + 3][wv] * PK[c + 3][x];
            }
            float e = __expf((s0 + s1) + (s2 + s3));
            Es[x][wv] = f2tf(e);
            sum += e;
        }
        ssum[half][wv] = sum;
    }
    __syncthreads();
    if (tid < 128) {
        float t = tot[((size_t)b * 128 + h) * 128 + tid];
        invs[tid] = 1.0f / (t + ssum[0][tid] + ssum[1][tid]);
    }

    // phase 3: V = pv @ E^T
    const int cm = tid >> 1;
    const int xq = (tid & 1) * 8;
    const float* pvp = pv + (((size_t)b * 128 + cm) * 128 + h) * 128;

    float acc[4][4][4] = {};
    float4 a0, a1;
    auto loadA = [&](int x0) {
        a0 = *(const float4*)(pvp + x0 + xq);
        a1 = *(const float4*)(pvp + x0 + xq + 4);
    };
    auto stA = [&](int buf) {
        As_[buf][xq + 0][cm] = f2tf(a0.x);
        As_[buf][xq + 1][cm] = f2tf(a0.y);
        As_[buf][xq + 2][cm] = f2tf(a0.z);
        As_[buf][xq + 3][cm] = f2tf(a0.w);
        As_[buf][xq + 4][cm] = f2tf(a1.x);
        As_[buf][xq + 5][cm] = f2tf(a1.y);
        As_[buf][xq + 6][cm] = f2tf(a1.z);
        As_[buf][xq + 7][cm] = f2tf(a1.w);
    };
    loadA(0); stA(0);
    __syncthreads();   // publishes Es, invs, As_[0]
    for (int kt = 0; kt < 8; kt++) {
        if (kt < 7) loadA((kt + 1) * 16);
        tile_mma(As_[kt & 1], (const unsigned(*)[136])&Es[kt * 16], acc, lane, mbase, nbase);
        if (kt < 7) stA((kt + 1) & 1);
        __syncthreads();
    }

    const float g = *gamma_p;
#pragma unroll
    for (int mt = 0; mt < 4; mt++)
#pragma unroll
        for (int half = 0; half < 2; half++) {
            int c = mbase + mt * 16 + (lane >> 2) + half * 8;
            size_t rowb = (((size_t)b * 128 + c) * 128 + h) * 128;
#pragma unroll
            for (int nt = 0; nt < 4; nt++) {
                int n = nbase + nt * 8 + 2 * (lane & 3);
                float2 t = *(const float2*)(tmp + rowb + n);
                float2 v = *(const float2*)(value + rowb + n);
                v.x += g * (t.x + acc[mt][nt][half * 2 + 0]) * invs[n];
                v.y += g * (t.y + acc[mt][nt][half * 2 + 1]) * invs[n + 1];
                *(float2*)(value + rowb + n) = v;
            }
        }
}

// ---------------- launch ----------------
extern "C" void kernel_launch(void* const* d_in, const int* in_sizes, int n_in,
                              void* d_out, int out_size)
{
    const float* low   = (const float*)d_in[0];
    const float* high  = (const float*)d_in[1];
    const float* Wc1   = (const float*)d_in[2];
    const float* bc1   = (const float*)d_in[3];
    const float* Wc2   = (const float*)d_in[4];
    const float* bc2   = (const float*)d_in[5];
    const float* Wq    = (const float*)d_in[6];
    const float* bq    = (const float*)d_in[7];
    const float* Wk    = (const float*)d_in[8];
    const float* bk    = (const float*)d_in[9];
    const float* Wv    = (const float*)d_in[10];
    const float* bv    = (const float*)d_in[11];
    const float* gamma = (const float*)d_in[12];
    const float* Wb    = (const float*)d_in[13];
    const float* bng   = (const float*)d_in[14];
    const float* bnb   = (const float*)d_in[15];
    const float* bnm   = (const float*)d_in[16];
    const float* bnv   = (const float*)d_in[17];
    float* out = (float*)d_out;

    float *highup, *query, *value, *pv, *tmp, *pq, *pk, *tot;
    cudaGetSymbolAddress((void**)&highup, g_highup);
    cudaGetSymbolAddress((void**)&query,  g_query);
    cudaGetSymbolAddress((void**)&value,  g_value);
    cudaGetSymbolAddress((void**)&pv,     g_pv);
    cudaGetSymbolAddress((void**)&tmp,    g_tmp);
    cudaGetSymbolAddress((void**)&pq,     g_pq);
    cudaGetSymbolAddress((void**)&pk,     g_pk);
    cudaGetSymbolAddress((void**)&tot,    g_tot);

    cudaFuncSetAttribute(fusedH_kernel, cudaFuncAttributeMaxDynamicSharedMemorySize, FUSED_SMEM);
    cudaFuncSetAttribute(fusedW_kernel, cudaFuncAttributeMaxDynamicSharedMemorySize, FUSED_SMEM);

    // 1. bilinear 2x upsample
    upsample_kernel<<<65536, 256>>>(high, highup);

    // 2. query = Wc1 @ concat(highup, low) + bc1
    gemm_dual<<<dim3(128, 1, BB), 256>>>(Wc1, 512, bc1, highup, 256, low, 256,
                                         query, 128, nullptr, nullptr, nullptr, nullptr);
    // 3. value = Wc2 @ highup + bc2
    gemm_dual<<<dim3(128, 1, BB), 256>>>(Wc2, 256, bc2, highup, 256, nullptr, 0,
                                         value, 128, nullptr, nullptr, nullptr, nullptr);

    // 4. pq (query fixed across iterations)
    proj16_kernel<<<dim3(64, BB), 256>>>(Wq, bq, query, pq);

    // 5. two criss-cross attention iterations, fully fused (att never hits HBM)
    for (int it = 0; it < 2; it++) {
        proj16_kernel<<<dim3(64, BB), 256>>>(Wk, bk, value, pk);
        gemm_dual<<<dim3(128, 1, BB), 256>>>(Wv, 128, bv, value, 128, nullptr, 0,
                                             pv, 128, nullptr, nullptr, nullptr, nullptr);
        fusedH_kernel<<<dim3(128, BB), 256, FUSED_SMEM>>>(pq, pk, pv, tot, tmp);
        fusedW_kernel<<<dim3(128, BB), 256, FUSED_SMEM>>>(pq, pk, pv, tot, tmp, value, gamma);
    }

    // 6. out = ReLU(BN(Wb @ concat(value, highup)))
    gemm_dual<<<dim3(128, 2, BB), 256>>>(Wb, 384, nullptr, value, 128, highup, 256,
                                         out, 256, bng, bnb, bnm, bnv);
}

// round 9
// speedup vs baseline: 1.0987x; 1.0987x over previous
#include <cuda_runtime.h>
#include <math.h>

#define BB   4
#define HWSZ 16384        // 128*128
#define NEGINF (-1000000000.0f)

// ---------------- scratch (device globals: no allocation allowed) ----------------
__device__ float g_fbu  [16777216];  // upsampled Wb_hi@high (4,256,128,128)
__device__ float g_value[ 8388608];  // (4,128,128,128)
__device__ float g_pv   [ 8388608];
__device__ float g_tmp  [ 8388608];
__device__ float g_pq   [ 1048576];  // (4,16,128,128)
__device__ float g_pk   [ 1048576];
__device__ float g_att  [16777216];  // (4,128,128,256)
__device__ float g_pqs  [  262144];  // (4,16,64,64)
__device__ float g_vs   [ 2097152];  // (4,128,64,64)
__device__ float g_fbs  [ 4194304];  // (4,256,64,64)
__device__ float g_weff [    8192];  // Wq@Wc1 (16,512)
__device__ float g_beff [      16];

// ---------------- tf32 helpers ----------------
__device__ __forceinline__ unsigned f2tf(float f) {
    unsigned r;
    asm("cvt.rna.tf32.f32 %0, %1;" : "=r"(r) : "f"(f));
    return r;
}

__device__ __forceinline__ void mma8(float* d, const unsigned* a, const unsigned* b) {
    asm("mma.sync.aligned.m16n8k8.row.col.f32.tf32.tf32.f32 "
        "{%0,%1,%2,%3},{%4,%5,%6,%7},{%8,%9},{%0,%1,%2,%3};"
        : "+f"(d[0]), "+f"(d[1]), "+f"(d[2]), "+f"(d[3])
        : "r"(a[0]), "r"(a[1]), "r"(a[2]), "r"(a[3]), "r"(b[0]), "r"(b[1]));
}

__device__ __forceinline__ void tile_mma(const unsigned (*As)[136],
                                         const unsigned (*Bs)[136],
                                         float acc[4][4][4],
                                         int lane, int mbase, int nbase)
{
#pragma unroll
    for (int kt = 0; kt < 2; kt++) {
        unsigned a[4][4], b[4][2];
        const int kb = kt * 8 + (lane & 3);
        const int rq = lane >> 2;
#pragma unroll
        for (int mt = 0; mt < 4; mt++) {
            int m = mbase + mt * 16 + rq;
            a[mt][0] = As[kb][m];
            a[mt][1] = As[kb][m + 8];
            a[mt][2] = As[kb + 4][m];
            a[mt][3] = As[kb + 4][m + 8];
        }
#pragma unroll
        for (int nt = 0; nt < 4; nt++) {
            int n = nbase + nt * 8 + rq;
            b[nt][0] = Bs[kb][n];
            b[nt][1] = Bs[kb + 4][n];
        }
#pragma unroll
        for (int mt = 0; mt < 4; mt++)
#pragma unroll
            for (int nt = 0; nt < 4; nt++)
                mma8(acc[mt][nt], a[mt], b[nt]);
    }
}

// ---------------- Wq_eff = Wq @ Wc1 ; b_eff = bq + Wq @ bc1 ----------------
__global__ __launch_bounds__(256) void prep_weff(
    const float* __restrict__ Wq, const float* __restrict__ Wc1,
    const float* __restrict__ bq, const float* __restrict__ bc1,
    float* __restrict__ weff, float* __restrict__ beff)
{
    int t = blockIdx.x * 256 + threadIdx.x;
    if (blockIdx.x < 32) {
        int o = t >> 9, j = t & 511;
        float s = 0.0f;
#pragma unroll 4
        for (int i = 0; i < 128; i++) s += Wq[o * 128 + i] * Wc1[i * 512 + j];
        weff[o * 512 + j] = s;
    } else if (threadIdx.x < 16) {
        int o = threadIdx.x;
        float s = bq[o];
        for (int i = 0; i < 128; i++) s += Wq[o * 128 + i] * bc1[i];
        beff[o] = s;
    }
}

// ---------------- bilinear 2x upsample (generic over channels via grid) ----------------
__global__ __launch_bounds__(256) void upsample_kernel(const float* __restrict__ in,
                                                       float* __restrict__ out) {
    int idx = blockIdx.x * 256 + threadIdx.x;
    int ox = idx & 127;
    int oy = (idx >> 7) & 127;
    int bc = idx >> 14;
    float fy = 0.5f * oy - 0.25f;
    float fx = 0.5f * ox - 0.25f;
    int y0 = (int)floorf(fy); float wy = fy - (float)y0;
    int x0 = (int)floorf(fx); float wx = fx - (float)x0;
    int y1 = min(y0 + 1, 63); y0 = max(y0, 0);
    int x1 = min(x0 + 1, 63); x0 = max(x0, 0);
    const float* p = in + (size_t)bc * 4096;
    float v00 = p[y0 * 64 + x0], v01 = p[y0 * 64 + x1];
    float v10 = p[y1 * 64 + x0], v11 = p[y1 * 64 + x1];
    float top = v00 + wx * (v01 - v00);
    float bot = v10 + wx * (v11 - v10);
    out[idx] = top + wy * (bot - top);
}

// ---------------- tf32 GEMM: Y[b,o,p] = W[o,:]@X[b,:,p] (+addin) (+BN/ReLU) ----------------
__global__ __launch_bounds__(256) void gemm_dual(
    const float* __restrict__ Wm, int ldw,
    const float* __restrict__ bias,
    const float* __restrict__ X, int I,
    float* __restrict__ Y, int O, int hw,
    const float* __restrict__ addin,
    const float* __restrict__ bng, const float* __restrict__ bnb,
    const float* __restrict__ bnm, const float* __restrict__ bnv)
{
    __shared__ unsigned As[16][136];
    __shared__ unsigned Bs[16][136];
    const int b  = blockIdx.z;
    const int to = blockIdx.y * 128;
    const int tp = blockIdx.x * 128;
    const int tid  = threadIdx.x;
    const int warp = tid >> 5;
    const int lane = tid & 31;
    const int mbase = (warp >> 2) * 64;
    const int nbase = (warp & 3) * 32;

    const int am  = tid >> 1;
    const int akq = (tid & 1) * 8;
    const int bk  = tid >> 4;
    const int bn  = (tid & 15) * 8;

    const float* Xp0 = X + (size_t)b * I * hw + tp + bn;

    float acc[4][4][4] = {};

    for (int k0 = 0; k0 < I; k0 += 16) {
        const float* Wp = Wm + (size_t)(to + am) * ldw + k0 + akq;
        float4 w0 = *(const float4*)Wp;
        float4 w1 = *(const float4*)(Wp + 4);
        const float* Xp = Xp0 + (size_t)(k0 + bk) * hw;
        float4 x0 = *(const float4*)Xp;
        float4 x1 = *(const float4*)(Xp + 4);

        __syncthreads();
        As[akq + 0][am] = f2tf(w0.x);
        As[akq + 1][am] = f2tf(w0.y);
        As[akq + 2][am] = f2tf(w0.z);
        As[akq + 3][am] = f2tf(w0.w);
        As[akq + 4][am] = f2tf(w1.x);
        As[akq + 5][am] = f2tf(w1.y);
        As[akq + 6][am] = f2tf(w1.z);
        As[akq + 7][am] = f2tf(w1.w);
        *(uint4*)&Bs[bk][bn]     = make_uint4(f2tf(x0.x), f2tf(x0.y), f2tf(x0.z), f2tf(x0.w));
        *(uint4*)&Bs[bk][bn + 4] = make_uint4(f2tf(x1.x), f2tf(x1.y), f2tf(x1.z), f2tf(x1.w));
        __syncthreads();

        tile_mma(As, Bs, acc, lane, mbase, nbase);
    }

    const bool dobn = (bng != nullptr);
#pragma unroll
    for (int mt = 0; mt < 4; mt++) {
#pragma unroll
        for (int half = 0; half < 2; half++) {
            int o = to + mbase + mt * 16 + (lane >> 2) + half * 8;
            float bia = bias ? bias[o] : 0.0f;
            float sc = 1.0f, mn = 0.0f, bt = 0.0f;
            if (dobn) {
                sc = bng[o] * rsqrtf(bnv[o] + 1e-5f);
                mn = bnm[o];
                bt = bnb[o];
            }
            size_t rowb = ((size_t)b * O + o) * hw + tp;
#pragma unroll
            for (int nt = 0; nt < 4; nt++) {
                int n = nbase + nt * 8 + 2 * (lane & 3);
                float v0 = acc[mt][nt][half * 2 + 0] + bia;
                float v1 = acc[mt][nt][half * 2 + 1] + bia;
                if (addin) {
                    float2 ad = *(const float2*)(addin + rowb + n);
                    v0 += ad.x; v1 += ad.y;
                }
                if (dobn) {
                    v0 = fmaxf((v0 - mn) * sc + bt, 0.0f);
                    v1 = fmaxf((v1 - mn) * sc + bt, 0.0f);
                }
                *(float2*)(Y + rowb + n) = make_float2(v0, v1);
            }
        }
    }
}

// ---------------- generic 16-output projection (optional accumulate) ----------------
__global__ __launch_bounds__(256) void proj16g(
    const float* __restrict__ Wm, int ldw,
    const float* __restrict__ bias,
    const float* __restrict__ X, int K, int hw,
    float* __restrict__ Y, int accum)
{
    __shared__ float Ws[16 * 256];
    const int b = blockIdx.y;
    const int p = blockIdx.x * 256 + threadIdx.x;
    for (int i = threadIdx.x; i < 16 * K; i += 256)
        Ws[i] = Wm[(i / K) * ldw + (i % K)];
    __syncthreads();
    float* Yp = Y + (size_t)b * 16 * hw + p;
    float acc[16];
#pragma unroll
    for (int o = 0; o < 16; o++)
        acc[o] = accum ? Yp[(size_t)o * hw] : (bias ? bias[o] : 0.0f);
    const float* Xp = X + (size_t)b * K * hw + p;
#pragma unroll 4
    for (int i = 0; i < K; i++) {
        float xv = Xp[(size_t)i * hw];
#pragma unroll
        for (int o = 0; o < 16; o++) acc[o] += Ws[o * K + i] * xv;
    }
#pragma unroll
    for (int o = 0; o < 16; o++) Yp[(size_t)o * hw] = acc[o];
}

// ---------------- criss-cross logits (R4-measured versions) ----------------
__global__ __launch_bounds__(256) void eH_kernel(const float* __restrict__ pq,
                                                 const float* __restrict__ pk,
                                                 float* __restrict__ att)
{
    __shared__ float PQ[16][128];
    __shared__ float PK[16][128];
    const int w = blockIdx.x, b = blockIdx.y;
    for (int i = threadIdx.x; i < 2048; i += 256) {
        int c = i >> 7, h = i & 127;
        size_t idx = (((size_t)b * 16 + c) * 128 + h) * 128 + w;
        PQ[c][h] = pq[idx];
        PK[c][h] = pk[idx];
    }
    __syncthreads();
    const int x  = threadIdx.x & 127;
    const int h0 = threadIdx.x >> 7;
    for (int h = h0; h < 128; h += 2) {
        float s = 0.0f;
#pragma unroll
        for (int c = 0; c < 16; c++) s += PQ[c][h] * PK[c][x];
        if (h == x) s += NEGINF;
        att[(((size_t)b * 128 + h) * 128 + w) * 256 + x] = s;
    }
}

__global__ __launch_bounds__(256) void eW_kernel(const float* __restrict__ pq,
                                                 const float* __restrict__ pk,
                                                 float* __restrict__ att)
{
    __shared__ float PQ[16][128];
    __shared__ float PK[16][128];
    const int h = blockIdx.x, b = blockIdx.y;
    for (int i = threadIdx.x; i < 2048; i += 256) {
        int c = i >> 7, w = i & 127;
        size_t idx = (((size_t)b * 16 + c) * 128 + h) * 128 + w;
        PQ[c][w] = pq[idx];
        PK[c][w] = pk[idx];
    }
    __syncthreads();
    const int x  = threadIdx.x & 127;
    const int w0 = threadIdx.x >> 7;
    for (int w = w0; w < 128; w += 2) {
        float s = 0.0f;
#pragma unroll
        for (int c = 0; c < 16; c++) s += PQ[c][w] * PK[c][x];
        att[(((size_t)b * 128 + h) * 128 + w) * 256 + 128 + x] = s;
    }
}

__global__ __launch_bounds__(256) void softmax_kernel(float* __restrict__ att)
{
    const int warp = threadIdx.x >> 5;
    const int lane = threadIdx.x & 31;
    const size_t row = (size_t)blockIdx.x * 8 + warp;
    float* r = att + row * 256;
    float v[8];
    float mx = -INFINITY;
#pragma unroll
    for (int j = 0; j < 8; j++) { v[j] = r[lane + 32 * j]; mx = fmaxf(mx, v[j]); }
#pragma unroll
    for (int o = 16; o; o >>= 1) mx = fmaxf(mx, __shfl_xor_sync(0xffffffffu, mx, o));
    float s = 0.0f;
#pragma unroll
    for (int j = 0; j < 8; j++) { v[j] = __expf(v[j] - mx); s += v[j]; }
#pragma unroll
    for (int o = 16; o; o >>= 1) s += __shfl_xor_sync(0xffffffffu, s, o);
    float inv = 1.0f / s;
#pragma unroll
    for (int j = 0; j < 8; j++) r[lane + 32 * j] = v[j] * inv;
}

// ---------------- aggH: tmp[b,c,h,w] = sum_x pv[b,c,x,w]*attH[b,h,w,x] ----------------
__global__ __launch_bounds__(256) void aggH_mma(const float* __restrict__ pv,
                                                const float* __restrict__ att,
                                                float* __restrict__ tmp)
{
    __shared__ unsigned As[16][136];
    __shared__ unsigned Bs[16][136];
    const int w = blockIdx.x, b = blockIdx.y;
    const int tid  = threadIdx.x;
    const int warp = tid >> 5;
    const int lane = tid & 31;
    const int mbase = (warp >> 2) * 64;
    const int nbase = (warp & 3) * 32;

    const int cm = tid >> 1;
    const int xq = (tid & 1) * 8;

    float acc[4][4][4] = {};
    const float* pvp = pv + ((size_t)b * 128 + cm) * HWSZ + w;
    const float* atp = att + (((size_t)b * 128 + cm) * 128 + w) * 256;

    for (int k0 = 0; k0 < 128; k0 += 16) {
        float av[8];
#pragma unroll
        for (int j = 0; j < 8; j++) av[j] = pvp[(size_t)(k0 + xq + j) * 128];
        float4 b0 = *(const float4*)(atp + k0 + xq);
        float4 b1 = *(const float4*)(atp + k0 + xq + 4);

        __syncthreads();
#pragma unroll
        for (int j = 0; j < 8; j++) As[xq + j][cm] = f2tf(av[j]);
        Bs[xq + 0][cm] = f2tf(b0.x);
        Bs[xq + 1][cm] = f2tf(b0.y);
        Bs[xq + 2][cm] = f2tf(b0.z);
        Bs[xq + 3][cm] = f2tf(b0.w);
        Bs[xq + 4][cm] = f2tf(b1.x);
        Bs[xq + 5][cm] = f2tf(b1.y);
        Bs[xq + 6][cm] = f2tf(b1.z);
        Bs[xq + 7][cm] = f2tf(b1.w);
        __syncthreads();

        tile_mma(As, Bs, acc, lane, mbase, nbase);
    }

#pragma unroll
    for (int mt = 0; mt < 4; mt++)
#pragma unroll
        for (int half = 0; half < 2; half++) {
            int c = mbase + mt * 16 + (lane >> 2) + half * 8;
            size_t cb = ((size_t)b * 128 + c) * HWSZ + w;
#pragma unroll
            for (int nt = 0; nt < 4; nt++) {
                int h = nbase + nt * 8 + 2 * (lane & 3);
                tmp[cb + (size_t)h * 128]       = acc[mt][nt][half * 2 + 0];
                tmp[cb + (size_t)(h + 1) * 128] = acc[mt][nt][half * 2 + 1];
            }
        }
}

// ---------------- aggW + update: value += gamma*(tmp + sum_x pv*attW) ----------------
__global__ __launch_bounds__(256) void aggW_mma(const float* __restrict__ pv,
                                                const float* __restrict__ att,
                                                const float* __restrict__ tmp,
                                                float* __restrict__ value,
                                                const float* __restrict__ gamma_p)
{
    __shared__ unsigned As[16][136];
    __shared__ unsigned Bs[16][136];
    const int h = blockIdx.x, b = blockIdx.y;
    const int tid  = threadIdx.x;
    const int warp = tid >> 5;
    const int lane = tid & 31;
    const int mbase = (warp >> 2) * 64;
    const int nbase = (warp & 3) * 32;

    const int cm = tid >> 1;
    const int xq = (tid & 1) * 8;

    float acc[4][4][4] = {};
    const float* pvp = pv + (((size_t)b * 128 + cm) * 128 + h) * 128;
    const float* atp = att + (((size_t)b * 128 + h) * 128 + cm) * 256 + 128;

    for (int k0 = 0; k0 < 128; k0 += 16) {
        float4 a0 = *(const float4*)(pvp + k0 + xq);
        float4 a1 = *(const float4*)(pvp + k0 + xq + 4);
        float4 b0 = *(const float4*)(atp + k0 + xq);
        float4 b1 = *(const float4*)(atp + k0 + xq + 4);

        __syncthreads();
        As[xq + 0][cm] = f2tf(a0.x);
        As[xq + 1][cm] = f2tf(a0.y);
        As[xq + 2][cm] = f2tf(a0.z);
        As[xq + 3][cm] = f2tf(a0.w);
        As[xq + 4][cm] = f2tf(a1.x);
        As[xq + 5][cm] = f2tf(a1.y);
        As[xq + 6][cm] = f2tf(a1.z);
        As[xq + 7][cm] = f2tf(a1.w);
        Bs[xq + 0][cm] = f2tf(b0.x);
        Bs[xq + 1][cm] = f2tf(b0.y);
        Bs[xq + 2][cm] = f2tf(b0.z);
        Bs[xq + 3][cm] = f2tf(b0.w);
        Bs[xq + 4][cm] = f2tf(b1.x);
        Bs[xq + 5][cm] = f2tf(b1.y);
        Bs[xq + 6][cm] = f2tf(b1.z);
        Bs[xq + 7][cm] = f2tf(b1.w);
        __syncthreads();

        tile_mma(As, Bs, acc, lane, mbase, nbase);
    }

    const float g = *gamma_p;
#pragma unroll
    for (int mt = 0; mt < 4; mt++)
#pragma unroll
        for (int half = 0; half < 2; half++) {
            int c = mbase + mt * 16 + (lane >> 2) + half * 8;
            size_t rowb = (((size_t)b * 128 + c) * 128 + h) * 128;
#pragma unroll
            for (int nt = 0; nt < 4; nt++) {
                int n = nbase + nt * 8 + 2 * (lane & 3);
                float2 t = *(const float2*)(tmp + rowb + n);
                float2 v = *(const float2*)(value + rowb + n);
                v.x += g * (t.x + acc[mt][nt][half * 2 + 0]);
                v.y += g * (t.y + acc[mt][nt][half * 2 + 1]);
                *(float2*)(value + rowb + n) = v;
            }
        }
}

// ---------------- launch ----------------
extern "C" void kernel_launch(void* const* d_in, const int* in_sizes, int n_in,
                              void* d_out, int out_size)
{
    const float* low   = (const float*)d_in[0];
    const float* high  = (const float*)d_in[1];
    const float* Wc1   = (const float*)d_in[2];
    const float* bc1   = (const float*)d_in[3];
    const float* Wc2   = (const float*)d_in[4];
    const float* bc2   = (const float*)d_in[5];
    const float* Wq    = (const float*)d_in[6];
    const float* bq    = (const float*)d_in[7];
    const float* Wk    = (const float*)d_in[8];
    const float* bk    = (const float*)d_in[9];
    const float* Wv    = (const float*)d_in[10];
    const float* bv    = (const float*)d_in[11];
    const float* gamma = (const float*)d_in[12];
    const float* Wb    = (const float*)d_in[13];
    const float* bng   = (const float*)d_in[14];
    const float* bnb   = (const float*)d_in[15];
    const float* bnm   = (const float*)d_in[16];
    const float* bnv   = (const float*)d_in[17];
    float* out = (float*)d_out;

    float *fbu, *value, *pv, *tmp, *pq, *pk, *att, *pqs, *vs, *fbs, *weff, *beff;
    cudaGetSymbolAddress((void**)&fbu,   g_fbu);
    cudaGetSymbolAddress((void**)&value, g_value);
    cudaGetSymbolAddress((void**)&pv,    g_pv);
    cudaGetSymbolAddress((void**)&tmp,   g_tmp);
    cudaGetSymbolAddress((void**)&pq,    g_pq);
    cudaGetSymbolAddress((void**)&pk,    g_pk);
    cudaGetSymbolAddress((void**)&att,   g_att);
    cudaGetSymbolAddress((void**)&pqs,   g_pqs);
    cudaGetSymbolAddress((void**)&vs,    g_vs);
    cudaGetSymbolAddress((void**)&fbs,   g_fbs);
    cudaGetSymbolAddress((void**)&weff,  g_weff);
    cudaGetSymbolAddress((void**)&beff,  g_beff);

    // 0. fold Wq through Wc1 (query tensor never materialized)
    prep_weff<<<33, 256>>>(Wq, Wc1, bq, bc1, weff, beff);

    // 1. pq = upsample(Wq_eff_hi @ high) + Wq_eff_lo @ low
    proj16g<<<dim3(16, BB), 256>>>(weff, 512, beff, high, 256, 4096, pqs, 0);
    upsample_kernel<<<4096, 256>>>(pqs, pq);
    proj16g<<<dim3(64, BB), 256>>>(weff + 256, 512, nullptr, low, 256, HWSZ, pq, 1);

    // 2. value = upsample(Wc2 @ high + bc2)   (conv1x1 commutes with upsample)
    gemm_dual<<<dim3(32, 1, BB), 256>>>(Wc2, 256, bc2, high, 256, vs, 128, 4096,
                                        nullptr, nullptr, nullptr, nullptr, nullptr);
    upsample_kernel<<<32768, 256>>>(vs, value);

    // 3. fbu = upsample(Wb[:,128:] @ high)    (final-gemm high half, folded small)
    gemm_dual<<<dim3(32, 2, BB), 256>>>(Wb + 128, 384, nullptr, high, 256, fbs, 256, 4096,
                                        nullptr, nullptr, nullptr, nullptr, nullptr);
    upsample_kernel<<<65536, 256>>>(fbs, fbu);

    // 4. two criss-cross attention iterations (R4-measured pipeline)
    for (int it = 0; it < 2; it++) {
        proj16g<<<dim3(64, BB), 256>>>(Wk, 128, bk, value, 128, HWSZ, pk, 0);
        gemm_dual<<<dim3(128, 1, BB), 256>>>(Wv, 128, bv, value, 128, pv, 128, HWSZ,
                                             nullptr, nullptr, nullptr, nullptr, nullptr);
        eH_kernel<<<dim3(128, BB), 256>>>(pq, pk, att);
        eW_kernel<<<dim3(128, BB), 256>>>(pq, pk, att);
        softmax_kernel<<<8192, 256>>>(att);
        aggH_mma<<<dim3(128, BB), 256>>>(pv, att, tmp);
        aggW_mma<<<dim3(128, BB), 256>>>(pv, att, tmp, value, gamma);
    }

    // 5. out = ReLU(BN(Wb[:,:128] @ value + fbu))
    gemm_dual<<<dim3(128, 2, BB), 256>>>(Wb, 384, nullptr, value, 128, out, 256, HWSZ,
                                         fbu, bng, bnb, bnm, bnv);
}